// round 12
// baseline (speedup 1.0000x reference)
#include <cuda_runtime.h>
#include <math.h>

#define NB      32
#define SAMPLES 5000
#define HW      (512 * 1024)
#define TOTAL   (NB * SAMPLES)          // 160000 pairs
#define SIGMA   0.03f
#define EPS     1e-6f

#define T1      256
#define B1      ((TOTAL + T1 - 1) / T1)  // 625

#define T2      256
#define B2      157                      // ~40192 threads for ~40k entries

// all zero-initialized at load; reset each call by kernel2's last block
__device__ int2         g_list[TOTAL];   // compacted valid pairs (gA, gB)
__device__ unsigned int g_list_cnt;
__device__ float        g_loss;
__device__ unsigned int g_done;

// ---------------- kernel 1: pure mask-gather flood + compaction ----------
__global__ void __launch_bounds__(T1) rl_mask_kernel(
    const int* __restrict__ mask,        // bool upcast to int32
    const int* __restrict__ idxA,
    const int* __restrict__ idxB)
{
    int i = blockIdx.x * blockDim.x + threadIdx.x;
    if (i >= TOTAL) return;

    int n    = i / SAMPLES;
    int base = n * HW;                   // fits in int (16.8M max)
    int gA = base + idxA[i];
    int gB = base + idxB[i];

    // dense unconditional gather stream (max DRAM efficiency)
    int mA = mask[gA];
    int mB = mask[gB];

    if (mA && mB) {
        // ptxas warp-aggregates this into REDUX + one ATOMS -> lanes get
        // consecutive slots -> semi-coalesced STG.64
        unsigned pos = atomicAdd(&g_list_cnt, 1u);
        g_list[pos] = make_int2(gA, gB);
    }
}

// ---------------- kernel 2: dense t/p-gather flood + compute + reduce ----
__global__ void __launch_bounds__(T2) rl_loss_kernel(
    const float* __restrict__ pred,
    const float* __restrict__ targ,
    float*       __restrict__ out)
{
    const unsigned cnt = g_list_cnt;     // kernel boundary makes this visible
    const float hi = 1.0f + SIGMA;
    const float lo = 1.0f / (1.0f + SIGMA);

    float loss = 0.0f;
    unsigned stride = gridDim.x * blockDim.x;
    for (unsigned e = blockIdx.x * blockDim.x + threadIdx.x; e < cnt; e += stride) {
        int2 g = g_list[e];              // coalesced LDG.64
        // 4 fully dense independent gathers
        float tA = targ[g.x];
        float tB = targ[g.y];
        float pA = pred[g.x];
        float pB = pred[g.y];

        float ratio = tA / (tB + EPS);
        if (ratio < hi && ratio > lo) {
            float d = pA - pB;
            loss += d * d;                          // equal branch (ALPHA=1)
        } else {
            float label = (ratio >= hi) ? 1.0f : -1.0f;
            float x = (pB - pA) * label;
            loss += (x > 20.0f) ? x : log1pf(expf(x));
        }
    }

    // --- block reduction ---
    #pragma unroll
    for (int off = 16; off > 0; off >>= 1)
        loss += __shfl_down_sync(0xffffffffu, loss, off);

    __shared__ float s_loss[8];
    __shared__ bool  s_last;
    int lane = threadIdx.x & 31;
    int wid  = threadIdx.x >> 5;
    if (lane == 0) s_loss[wid] = loss;
    __syncthreads();

    if (wid == 0) {
        loss = (lane < (T2 / 32)) ? s_loss[lane] : 0.0f;
        #pragma unroll
        for (int off = 4; off > 0; off >>= 1)
            loss += __shfl_down_sync(0xffffffffu, loss, off);
        if (lane == 0) {
            atomicAdd(&g_loss, loss);
            __threadfence();
            unsigned ticket = atomicAdd(&g_done, 1u);
            s_last = (ticket == (unsigned)(gridDim.x - 1));
        }
    }
    __syncthreads();

    // last block finalizes and resets all state for the next graph replay
    if (s_last && threadIdx.x == 0) {
        out[0] = g_loss / ((float)cnt + EPS);   // ALPHA = LOSS_WEIGHT = 1
        g_loss     = 0.0f;
        g_done     = 0u;
        __threadfence();
        g_list_cnt = 0u;
    }
}

extern "C" void kernel_launch(void* const* d_in, const int* in_sizes, int n_in,
                              void* d_out, int out_size)
{
    const float* pred = (const float*)d_in[0];
    const float* targ = (const float*)d_in[1];
    const int*   mask = (const int*)d_in[2];
    const int*   idxA = (const int*)d_in[3];
    const int*   idxB = (const int*)d_in[4];
    float* out = (float*)d_out;

    rl_mask_kernel<<<B1, T1>>>(mask, idxA, idxB);
    rl_loss_kernel<<<B2, T2>>>(pred, targ, out);
}

// round 13
// speedup vs baseline: 1.3882x; 1.3882x over previous
#include <cuda_runtime.h>
#include <math.h>

#define NB      32
#define SAMPLES 5000u
#define HW      (512 * 1024)
#define TOTAL   (NB * 5000)             // 160000 pairs
#define K       5                        // pairs per thread
#define NTHR    (TOTAL / K)              // 32000 threads
#define THREADS 256
#define BLOCKS  (NTHR / THREADS)         // 125 exactly
#define SIGMA   0.03f
#define EPS     1e-6f

// zero-initialized at load; reset by last block each call (graph-safe)
__device__ float        g_acc[2];        // [0]=loss sum, [1]=valid count
__device__ unsigned int g_count;

__global__ void __launch_bounds__(THREADS) rl_fused10_kernel(
    const float* __restrict__ pred,
    const float* __restrict__ targ,
    const int*   __restrict__ mask,      // bool upcast to int32 by harness
    const int*   __restrict__ idxA,
    const int*   __restrict__ idxB,
    float*       __restrict__ out)
{
    unsigned t = blockIdx.x * blockDim.x + threadIdx.x;   // < NTHR always

    // pure 32-bit addressing: all offsets < 16.8M
    int gA[K], gB[K];
    #pragma unroll
    for (int j = 0; j < K; j++) {
        unsigned pair = t + (unsigned)j * (unsigned)NTHR;  // coalesced
        unsigned n    = pair / SAMPLES;
        int base = (int)n * HW;
        gA[j] = base + idxA[pair];
        gB[j] = base + idxB[pair];
    }

    // phase A: 2K independent mask gathers, all in flight together (MLP=10)
    int mA[K], mB[K];
    #pragma unroll
    for (int j = 0; j < K; j++) {
        mA[j] = mask[gA[j]];
        mB[j] = mask[gB[j]];
    }

    bool cm[K];
    #pragma unroll
    for (int j = 0; j < K; j++) cm[j] = (mA[j] != 0) && (mB[j] != 0);

    // phase B: all conditional t/p gathers batched (predicated LDGs)
    float tA[K], tB[K], pA[K], pB[K];
    #pragma unroll
    for (int j = 0; j < K; j++) {
        tA[j] = 1.0f; tB[j] = 1.0f; pA[j] = 0.0f; pB[j] = 0.0f;
        if (cm[j]) {
            tA[j] = targ[gA[j]];
            tB[j] = targ[gB[j]];
            pA[j] = pred[gA[j]];
            pB[j] = pred[gB[j]];
        }
    }

    // compute
    float loss = 0.0f, valid = 0.0f;
    const float hi = 1.0f + SIGMA;
    const float lo = 1.0f / (1.0f + SIGMA);
    #pragma unroll
    for (int j = 0; j < K; j++) {
        if (cm[j]) {
            valid += 1.0f;
            float ratio = tA[j] / (tB[j] + EPS);
            if (ratio < hi && ratio > lo) {
                float d = pA[j] - pB[j];
                loss += d * d;                        // equal branch (ALPHA=1)
            } else {
                float label = (ratio >= hi) ? 1.0f : -1.0f;
                float x = (pB[j] - pA[j]) * label;
                loss += (x > 20.0f) ? x : log1pf(expf(x));
            }
        }
    }

    // --- block reduction of (loss, valid) ---
    #pragma unroll
    for (int off = 16; off > 0; off >>= 1) {
        loss  += __shfl_down_sync(0xffffffffu, loss,  off);
        valid += __shfl_down_sync(0xffffffffu, valid, off);
    }

    __shared__ float s_loss[8], s_valid[8];
    __shared__ bool  s_last;
    int lane = threadIdx.x & 31;
    int wid  = threadIdx.x >> 5;
    if (lane == 0) {
        s_loss[wid]  = loss;
        s_valid[wid] = valid;
    }
    __syncthreads();

    if (wid == 0) {
        loss  = (lane < (THREADS / 32)) ? s_loss[lane]  : 0.0f;
        valid = (lane < (THREADS / 32)) ? s_valid[lane] : 0.0f;
        #pragma unroll
        for (int off = 4; off > 0; off >>= 1) {
            loss  += __shfl_down_sync(0xffffffffu, loss,  off);
            valid += __shfl_down_sync(0xffffffffu, valid, off);
        }
        if (lane == 0) {
            atomicAdd(&g_acc[0], loss);
            atomicAdd(&g_acc[1], valid);
            __threadfence();
            unsigned ticket = atomicAdd(&g_count, 1u);
            s_last = (ticket == (unsigned)(gridDim.x - 1));
        }
    }
    __syncthreads();

    // last block finalizes and resets state for next graph replay
    if (s_last && threadIdx.x == 0) {
        float l = g_acc[0], v = g_acc[1];
        out[0] = l / (v + EPS);           // ALPHA = LOSS_WEIGHT = 1
        g_acc[0] = 0.0f;
        g_acc[1] = 0.0f;
        __threadfence();
        g_count = 0u;
    }
}

extern "C" void kernel_launch(void* const* d_in, const int* in_sizes, int n_in,
                              void* d_out, int out_size)
{
    const float* pred = (const float*)d_in[0];
    const float* targ = (const float*)d_in[1];
    const int*   mask = (const int*)d_in[2];
    const int*   idxA = (const int*)d_in[3];
    const int*   idxB = (const int*)d_in[4];
    float* out = (float*)d_out;

    rl_fused10_kernel<<<BLOCKS, THREADS>>>(pred, targ, mask, idxA, idxB, out);
}